// round 10
// baseline (speedup 1.0000x reference)
#include <cuda_runtime.h>
#include <cuda_fp16.h>
#include <cstdint>

// ---------------- problem constants ----------------
#define BB    16
#define KK    2048
#define DD    512
#define INNER 1024
#define W2    (2*INNER)    // combined a|b row stride (halves)
#define ST    (W2/2)       // half2 stride per k (1024)
#define KW    5
#define MM    (BB*KK)      // 32768
#define EPSV  1e-5f
#define NC    64           // scan chunks per sequence
#define CL    (KK/NC)      // 32
#define IH    (INNER/2)    // 512 half2 per inner row
#define NBLK  (BB*NC*2)    // 2048 scan blocks

// ---------------- scratch (device globals) ----------------
__device__ __half  g_ab [(size_t)MM * W2];     // [M, 2048]: a | b (fp16) 128MB
__device__ __half  g_h16[(size_t)MM * DD];     // rmsnorm out (fp16)
__device__ __half  g_g16[(size_t)MM * INNER];  // scan out    (fp16)
__device__ __half  g_w2 [W2 * DD];             // [Wa;Wb] fp16
__device__ __half  g_wo16[DD * INNER];
__device__ float2  g_sloc[NBLK][256];          // chunk-local states
__device__ float2  g_sinc[NBLK][256];          // inclusive states
__device__ int     g_flag[NBLK];               // 0=none, 1=local, 2=inclusive

__device__ __forceinline__ uint32_t smem_u32(const void* p) {
    uint32_t a;
    asm("{ .reg .u64 t; cvta.to.shared.u64 t, %1; cvt.u32.u64 %0, t; }"
        : "=r"(a) : "l"(p));
    return a;
}

// ---------------- rmsnorm -> fp16 ----------------
__global__ __launch_bounds__(256) void rmsnorm_kernel(
    const float* __restrict__ x, const float* __restrict__ w,
    __half* __restrict__ h16)
{
    int row  = blockIdx.x * 8 + (threadIdx.x >> 5);
    int lane = threadIdx.x & 31;
    const float4* xp = reinterpret_cast<const float4*>(x + (size_t)row * DD);
    const float4* wp = reinterpret_cast<const float4*>(w);

    float4 v[4];
    float ss = 0.f;
#pragma unroll
    for (int j = 0; j < 4; j++) {
        v[j] = xp[lane + 32 * j];
        ss += v[j].x * v[j].x + v[j].y * v[j].y + v[j].z * v[j].z + v[j].w * v[j].w;
    }
#pragma unroll
    for (int off = 16; off > 0; off >>= 1)
        ss += __shfl_xor_sync(0xffffffffu, ss, off);

    float r = rsqrtf(ss * (1.0f / DD) + EPSV);

    __half* hb = h16 + (size_t)row * DD;
#pragma unroll
    for (int j = 0; j < 4; j++) {
        float4 wv = wp[lane + 32 * j];
        int col = (lane + 32 * j) * 4;
        __half2* hp = reinterpret_cast<__half2*>(hb + col);
        hp[0] = __floats2half2_rn(v[j].x * r * wv.x, v[j].y * r * wv.y);
        hp[1] = __floats2half2_rn(v[j].z * r * wv.z, v[j].w * r * wv.w);
    }
}

// ---------------- fp32 -> fp16 cast (weights), vectorized ----------------
__global__ __launch_bounds__(256) void cvt_kernel(
    const float* __restrict__ src, __half* __restrict__ dst, int n4)
{
    int i = blockIdx.x * 256 + threadIdx.x;
    if (i < n4) {
        float4 v = reinterpret_cast<const float4*>(src)[i];
        __half2* d = reinterpret_cast<__half2*>(dst) + i * 2;
        d[0] = __floats2half2_rn(v.x, v.y);
        d[1] = __floats2half2_rn(v.z, v.w);
    }
}

// ---------------- HMMA fp16 GEMM with ldmatrix, 3-stage pipeline ------------
#define RS 40
#define TILE_H (128 * RS)
#define TB (TILE_H * 2)
#define STAGE_B (2 * TB)
#define NSTAGE 3
#define GEMM_SMEM_BYTES (NSTAGE * STAGE_B)   // 61440

#define MMA_F16(c, a, b)                                                \
    asm volatile(                                                       \
        "mma.sync.aligned.m16n8k16.row.col.f32.f16.f16.f32 "            \
        "{%0,%1,%2,%3}, {%4,%5,%6,%7}, {%8,%9}, {%0,%1,%2,%3};"         \
        : "+f"((c)[0]), "+f"((c)[1]), "+f"((c)[2]), "+f"((c)[3])        \
        : "r"((a)[0]), "r"((a)[1]), "r"((a)[2]), "r"((a)[3]),           \
          "r"((b)[0]), "r"((b)[1]))

#define LDSM4(r0, r1, r2, r3, addr)                                     \
    asm volatile("ldmatrix.sync.aligned.m8n8.x4.shared.b16 "            \
                 "{%0,%1,%2,%3}, [%4];"                                 \
                 : "=r"(r0), "=r"(r1), "=r"(r2), "=r"(r3) : "r"(addr))

template <bool HALF_OUT>
__global__ __launch_bounds__(256, 2) void gemm_f16(
    const __half* __restrict__ A, const __half* __restrict__ B,
    void* __restrict__ Cv, const float* __restrict__ res, int N, int K)
{
    extern __shared__ uint16_t sm[];

    const int tid  = threadIdx.x;
    const int lane = tid & 31;
    const int wid  = tid >> 5;
    const int wm   = wid >> 2;
    const int wn   = wid & 3;
    const int r    = lane >> 2;
    const int cp   = (lane & 3) * 2;

    const size_t mBase = (size_t)blockIdx.y * 128;
    const size_t nBase = (size_t)blockIdx.x * 128;

    const __half* srcA = A + mBase * K;
    const __half* srcB = B + nBase * K;

    const uint32_t smem_base = smem_u32(sm);

    const uint32_t aLaneOff =
        (uint32_t)(((wm * 64 + ((lane >> 3) & 1) * 8 + (lane & 7)) * RS
                    + (lane >> 4) * 8) * 2);
    const uint32_t bLaneOff =
        (uint32_t)(((wn * 32 + ((lane >> 4) & 1) * 8 + (lane & 7)) * RS
                    + ((lane >> 3) & 1) * 8) * 2);

    const int lrow0 = tid >> 2;
    const int lseg  = tid & 3;
    auto load_stage = [&](int s, int kt) {
        uint32_t sb = smem_base + (uint32_t)s * STAGE_B;
#pragma unroll
        for (int rep = 0; rep < 2; rep++) {
            int row = lrow0 + rep * 64;
            uint32_t off = row * (RS * 2) + lseg * 16;
            size_t go = (size_t)row * K + kt * 32 + lseg * 8;
            asm volatile("cp.async.cg.shared.global [%0], [%1], 16;"
                         :: "r"(sb + off), "l"(srcA + go));
            asm volatile("cp.async.cg.shared.global [%0], [%1], 16;"
                         :: "r"(sb + TB + off), "l"(srcB + go));
        }
        asm volatile("cp.async.commit_group;" ::: "memory");
    };

    float acc[4][4][4];
#pragma unroll
    for (int i = 0; i < 4; i++)
#pragma unroll
        for (int j = 0; j < 4; j++)
#pragma unroll
            for (int q = 0; q < 4; q++) acc[i][j][q] = 0.f;

    const int nkt = K >> 5;

    load_stage(0, 0);
    load_stage(1, 1);

    int sc = 0;
    for (int kt = 0; kt < nkt; kt++) {
        if (kt + 1 < nkt) {
            asm volatile("cp.async.wait_group 1;" ::: "memory");
        } else {
            asm volatile("cp.async.wait_group 0;" ::: "memory");
        }
        __syncthreads();

        if (kt + 2 < nkt) {
            int s2 = sc + 2; if (s2 >= NSTAGE) s2 -= NSTAGE;
            load_stage(s2, kt + 2);
        }

        uint32_t sb = smem_base + (uint32_t)sc * STAGE_B;

#pragma unroll
        for (int k16 = 0; k16 < 32; k16 += 16) {
            uint32_t bh[4][2];
#pragma unroll
            for (int j = 0; j < 2; j++) {
                uint32_t ad = sb + TB + bLaneOff
                            + (uint32_t)((j * 16 * RS + k16) * 2);
                LDSM4(bh[2*j][0], bh[2*j][1], bh[2*j+1][0], bh[2*j+1][1], ad);
            }
#pragma unroll
            for (int mi = 0; mi < 4; mi++) {
                uint32_t a4[4];
                uint32_t ad = sb + aLaneOff + (uint32_t)((mi * 16 * RS + k16) * 2);
                LDSM4(a4[0], a4[1], a4[2], a4[3], ad);
#pragma unroll
                for (int ni = 0; ni < 4; ni++)
                    MMA_F16(acc[mi][ni], a4, bh[ni]);
            }
        }
        __syncthreads();
        if (++sc == NSTAGE) sc = 0;
    }

#pragma unroll
    for (int mi = 0; mi < 4; mi++) {
        size_t row0 = mBase + wm * 64 + mi * 16 + r;
#pragma unroll
        for (int ni = 0; ni < 4; ni++) {
            size_t col = nBase + wn * 32 + ni * 8 + cp;
            if (HALF_OUT) {
                __half* C = (__half*)Cv;
                *reinterpret_cast<__half2*>(C + row0 * N + col) =
                    __floats2half2_rn(acc[mi][ni][0], acc[mi][ni][1]);
                *reinterpret_cast<__half2*>(C + (row0 + 8) * N + col) =
                    __floats2half2_rn(acc[mi][ni][2], acc[mi][ni][3]);
            } else {
                float* C = (float*)Cv;
                float2 v0 = make_float2(acc[mi][ni][0], acc[mi][ni][1]);
                float2 v1 = make_float2(acc[mi][ni][2], acc[mi][ni][3]);
                if (res) {
                    float2 r0 = *reinterpret_cast<const float2*>(res + row0 * N + col);
                    float2 r1 = *reinterpret_cast<const float2*>(res + (row0 + 8) * N + col);
                    v0.x += r0.x; v0.y += r0.y;
                    v1.x += r1.x; v1.y += r1.y;
                }
                *reinterpret_cast<float2*>(C + row0 * N + col) = v0;
                *reinterpret_cast<float2*>(C + (row0 + 8) * N + col) = v1;
            }
        }
    }
}

// ---------------- fused single-pass scan with decoupled lookback ------------
// Block = (batch, chunk, channel-half). 256 threads, one half2 pair each.
__global__ __launch_bounds__(256) void scan_fused_kernel(
    const __half2* __restrict__ ab2,
    __half2* __restrict__ g2,
    const float* __restrict__ conv_w, const float* __restrict__ conv_b,
    const float* __restrict__ alpha, const float* __restrict__ beta,
    const float* __restrict__ gamma, const float* __restrict__ delta)
{
    const int blk  = blockIdx.x;
    const int half = blk & 1;
    const int c    = (blk >> 1) & (NC - 1);
    const int b    = blk >> 7;                 // /(NC*2)
    const int tid  = threadIdx.x;
    const int i2   = half * 256 + tid;
    const int i0   = i2 * 2;

    float2 w0 = make_float2(conv_w[i0*KW+0], conv_w[i0*KW+KW+0]);
    float2 w1 = make_float2(conv_w[i0*KW+1], conv_w[i0*KW+KW+1]);
    float2 w2 = make_float2(conv_w[i0*KW+2], conv_w[i0*KW+KW+2]);
    float2 w3 = make_float2(conv_w[i0*KW+3], conv_w[i0*KW+KW+3]);
    float2 w4 = make_float2(conv_w[i0*KW+4], conv_w[i0*KW+KW+4]);
    float2 cb = make_float2(conv_b[i0], conv_b[i0+1]);
    float2 as = make_float2(1.0f/(1.0f+__expf(-alpha[i0])),
                            1.0f/(1.0f+__expf(-alpha[i0+1])));
    float2 bt = make_float2(beta[i0],  beta[i0+1]);
    float2 gm = make_float2(gamma[i0], gamma[i0+1]);
    float2 dl = make_float2(delta[i0], delta[i0+1]);

    float2 aL = as;                            // as^CL = as^32
#pragma unroll
    for (int q = 0; q < 5; q++) { aL.x *= aL.x; aL.y *= aL.y; }

    const __half2* col = ab2 + (size_t)b * KK * ST + i2;
    const __half2* bp  = col + IH;
    __half2* gp = g2 + (size_t)b * KK * IH + i2;
    const int k0 = c * CL;

    // ---- phase 1: conv + silu -> u (regs) + chunk-local state ----
    float2 xm2 = (c > 0) ? __half22float2(col[(size_t)(k0-2) * ST]) : make_float2(0.f,0.f);
    float2 xm1 = (c > 0) ? __half22float2(col[(size_t)(k0-1) * ST]) : make_float2(0.f,0.f);
    float2 x0 = __half22float2(col[(size_t)k0 * ST]);
    float2 x1 = __half22float2(col[(size_t)(k0+1) * ST]);

    __half2 ureg[CL];
    float2 sloc = make_float2(0.f, 0.f);

#pragma unroll
    for (int k = 0; k < CL; k += 8) {
        float2 xn[8];
#pragma unroll
        for (int j = 0; j < 8; j++) {
            int kk = k0 + k + 2 + j;
            xn[j] = (kk < KK) ? __half22float2(col[(size_t)kk * ST])
                              : make_float2(0.f, 0.f);
        }
#pragma unroll
        for (int j = 0; j < 8; j++) {
            float2 x2 = xn[j];
            float cx = fmaf(w0.x, xm2.x, fmaf(w1.x, xm1.x, fmaf(w2.x, x0.x,
                       fmaf(w3.x, x1.x, fmaf(w4.x, x2.x, cb.x)))));
            float cy = fmaf(w0.y, xm2.y, fmaf(w1.y, xm1.y, fmaf(w2.y, x0.y,
                       fmaf(w3.y, x1.y, fmaf(w4.y, x2.y, cb.y)))));
            float ux = __fdividef(cx, 1.0f + __expf(-cx));
            float uy = __fdividef(cy, 1.0f + __expf(-cy));
            ureg[k + j] = __floats2half2_rn(ux, uy);
            sloc.x = fmaf(as.x, sloc.x, bt.x * ux);
            sloc.y = fmaf(as.y, sloc.y, bt.y * uy);
            xm2 = xm1; xm1 = x0; x0 = x1; x1 = x2;
        }
    }

    // ---- publish local ----
    g_sloc[blk][tid] = sloc;
    __syncthreads();
    if (tid == 0) {
        __threadfence();
        atomicExch(&g_flag[blk], (c == 0) ? 2 : 1);   // c==0: local==inclusive? no...
    }
    // NOTE: for c==0 inclusive == local; write sinc too before flag=2.
    // (handled below: we recompute & publish inclusive for all blocks)

    // ---- phase 2: lookback for prefix S = s_inc(c-1) ----
    __shared__ int sflag;
    float2 S = make_float2(0.f, 0.f);
    if (c > 0) {
        float2 mult = make_float2(1.f, 1.f);
        int pred = blk - 2;
        while (true) {
            if (tid == 0) {
                int f;
                do {
                    f = *(volatile int*)&g_flag[pred];
                    if (f == 0) __nanosleep(64);
                } while (f == 0);
                sflag = f;
            }
            __syncthreads();
            int f = sflag;
            __threadfence();
            float2 sv = (f == 2) ? g_sinc[pred][tid] : g_sloc[pred][tid];
            S.x = fmaf(mult.x, sv.x, S.x);
            S.y = fmaf(mult.y, sv.y, S.y);
            __syncthreads();
            if (f == 2) break;
            mult.x *= aL.x; mult.y *= aL.y;
            pred -= 2;
        }
    }

    // ---- publish inclusive: s_inc = sloc + aL * S ----
    g_sinc[blk][tid] = make_float2(fmaf(aL.x, S.x, sloc.x),
                                   fmaf(aL.y, S.y, sloc.y));
    __syncthreads();
    if (tid == 0) {
        __threadfence();
        atomicExch(&g_flag[blk], 2);
    }

    // ---- phase 3: apply with prefix, gate, store ----
    float2 s = S;
#pragma unroll
    for (int k = 0; k < CL; k += 8) {
        float2 bb[8];
#pragma unroll
        for (int j = 0; j < 8; j++)
            bb[j] = __half22float2(bp[(size_t)(k0 + k + j) * ST]);
#pragma unroll
        for (int j = 0; j < 8; j++) {
            float2 u = __half22float2(ureg[k + j]);
            s.x = fmaf(as.x, s.x, bt.x * u.x);
            s.y = fmaf(as.y, s.y, bt.y * u.y);
            float yx = fmaf(gm.x, s.x, dl.x * u.x);
            float yy = fmaf(gm.y, s.y, dl.y * u.y);
            gp[(size_t)(k0 + k + j) * IH] =
                __floats2half2_rn(yx * bb[j].x, yy * bb[j].y);
        }
    }
}

// ---------------- launch ----------------
extern "C" void kernel_launch(void* const* d_in, const int* in_sizes, int n_in,
                              void* d_out, int out_size)
{
    const float* x      = (const float*)d_in[0];
    const float* norm_w = (const float*)d_in[1];
    const float* Wa     = (const float*)d_in[2];
    const float* Wb     = (const float*)d_in[3];
    const float* conv_w = (const float*)d_in[4];
    const float* conv_b = (const float*)d_in[5];
    const float* alpha  = (const float*)d_in[6];
    const float* beta   = (const float*)d_in[7];
    const float* gamma  = (const float*)d_in[8];
    const float* delta  = (const float*)d_in[9];
    const float* Wout   = (const float*)d_in[10];
    float* out = (float*)d_out;

    __half *ab, *h16, *g16, *w2, *wo16;
    int* flags;
    cudaGetSymbolAddress((void**)&ab,    g_ab);
    cudaGetSymbolAddress((void**)&h16,   g_h16);
    cudaGetSymbolAddress((void**)&g16,   g_g16);
    cudaGetSymbolAddress((void**)&w2,    g_w2);
    cudaGetSymbolAddress((void**)&wo16,  g_wo16);
    cudaGetSymbolAddress((void**)&flags, g_flag);

    cudaFuncSetAttribute(gemm_f16<true>,
                         cudaFuncAttributeMaxDynamicSharedMemorySize, GEMM_SMEM_BYTES);
    cudaFuncSetAttribute(gemm_f16<false>,
                         cudaFuncAttributeMaxDynamicSharedMemorySize, GEMM_SMEM_BYTES);

    // 1) rmsnorm -> fp16
    rmsnorm_kernel<<<MM / 8, 256>>>(x, norm_w, h16);

    // 2) weight conversions (fp16): [Wa;Wb] combined + Wout
    cvt_kernel<<<(INNER * DD / 4 + 255) / 256, 256>>>(Wa, w2, INNER * DD / 4);
    cvt_kernel<<<(INNER * DD / 4 + 255) / 256, 256>>>(Wb, w2 + (size_t)INNER * DD, INNER * DD / 4);
    cvt_kernel<<<(DD * INNER / 4 + 255) / 256, 256>>>(Wout, wo16, DD * INNER / 4);

    // 3) [a|b] = h @ [Wa;Wb]^T   (M=32768, N=2048, K=512), fp16 out
    {
        dim3 grid(W2 / 128, MM / 128);
        gemm_f16<true><<<grid, 256, GEMM_SMEM_BYTES>>>(h16, w2, ab, nullptr, W2, DD);
    }

    // 4) fused single-pass scan (conv + silu + scan + gate)
    scan_fused_kernel<<<NBLK, 256>>>(
        (const __half2*)ab, (__half2*)g16,
        conv_w, conv_b, alpha, beta, gamma, delta);

    // 5) out = x + g @ Wout^T   (M=32768, N=512, K=1024), fp32 out + residual
    {
        dim3 grid(DD / 128, MM / 128);
        gemm_f16<false><<<grid, 256, GEMM_SMEM_BYTES>>>(g16, wo16, out, x, DD, INNER);
    }
}

// round 11
// speedup vs baseline: 1.0163x; 1.0163x over previous
#include <cuda_runtime.h>
#include <cuda_fp16.h>
#include <cstdint>

// ---------------- problem constants ----------------
#define BB    16
#define KK    2048
#define DD    512
#define INNER 1024
#define W2    (2*INNER)    // combined a|b row stride (halves)
#define KW    5
#define MM    (BB*KK)      // 32768
#define EPSV  1e-5f
#define NC    64           // scan chunks
#define CL    (KK/NC)      // 32
#define RSU2  (W2/4)       // uint2 per ab row (512)
#define USU2  (INNER/4)    // uint2 per u/g row (256)

// ---------------- scratch (device globals) ----------------
__device__ __half  g_ab [(size_t)MM * W2];     // [M, 2048]: a | b (fp16) 128MB
__device__ __half  g_u  [(size_t)MM * INNER];  // conv+silu out (fp16)  64MB
__device__ __half  g_h16[(size_t)MM * DD];     // rmsnorm out (fp16)
__device__ __half  g_g16[(size_t)MM * INNER];  // scan out    (fp16)
__device__ __half  g_w2 [W2 * DD];             // [Wa;Wb] fp16
__device__ __half  g_wo16[DD * INNER];
__device__ float   g_state[BB * NC * INNER];   // chunk-local final states
__device__ float   g_sin  [BB * NC * INNER];   // carried-in states

__device__ __forceinline__ uint32_t smem_u32(const void* p) {
    uint32_t a;
    asm("{ .reg .u64 t; cvta.to.shared.u64 t, %1; cvt.u32.u64 %0, t; }"
        : "=r"(a) : "l"(p));
    return a;
}

// 4-half <-> 4-float helpers
__device__ __forceinline__ void h4_to_f4(uint2 v, float* f) {
    __half2 lo = *reinterpret_cast<__half2*>(&v.x);
    __half2 hi = *reinterpret_cast<__half2*>(&v.y);
    float2 a = __half22float2(lo), b = __half22float2(hi);
    f[0] = a.x; f[1] = a.y; f[2] = b.x; f[3] = b.y;
}
__device__ __forceinline__ uint2 f4_to_h4(const float* f) {
    __half2 lo = __floats2half2_rn(f[0], f[1]);
    __half2 hi = __floats2half2_rn(f[2], f[3]);
    uint2 r;
    r.x = *reinterpret_cast<uint32_t*>(&lo);
    r.y = *reinterpret_cast<uint32_t*>(&hi);
    return r;
}

// ---------------- rmsnorm -> fp16 ----------------
__global__ __launch_bounds__(256) void rmsnorm_kernel(
    const float* __restrict__ x, const float* __restrict__ w,
    __half* __restrict__ h16)
{
    int row  = blockIdx.x * 8 + (threadIdx.x >> 5);
    int lane = threadIdx.x & 31;
    const float4* xp = reinterpret_cast<const float4*>(x + (size_t)row * DD);
    const float4* wp = reinterpret_cast<const float4*>(w);

    float4 v[4];
    float ss = 0.f;
#pragma unroll
    for (int j = 0; j < 4; j++) {
        v[j] = xp[lane + 32 * j];
        ss += v[j].x * v[j].x + v[j].y * v[j].y + v[j].z * v[j].z + v[j].w * v[j].w;
    }
#pragma unroll
    for (int off = 16; off > 0; off >>= 1)
        ss += __shfl_xor_sync(0xffffffffu, ss, off);

    float r = rsqrtf(ss * (1.0f / DD) + EPSV);

    __half* hb = h16 + (size_t)row * DD;
#pragma unroll
    for (int j = 0; j < 4; j++) {
        float4 wv = wp[lane + 32 * j];
        int col = (lane + 32 * j) * 4;
        __half2* hp = reinterpret_cast<__half2*>(hb + col);
        hp[0] = __floats2half2_rn(v[j].x * r * wv.x, v[j].y * r * wv.y);
        hp[1] = __floats2half2_rn(v[j].z * r * wv.z, v[j].w * r * wv.w);
    }
}

// ---------------- combined fp32 -> fp16 cast (all three weights) ------------
#define CVT_N4 (INNER * DD / 4)     // float4 count per weight tensor (131072)
__global__ __launch_bounds__(256) void cvt_all_kernel(
    const float* __restrict__ Wa, const float* __restrict__ Wb,
    const float* __restrict__ Wo,
    __half* __restrict__ w2, __half* __restrict__ wo16)
{
    int i = blockIdx.x * 256 + threadIdx.x;
    const float* src;
    __half* dst;
    int o;
    if (i < CVT_N4)            { src = Wa; dst = w2;                        o = i; }
    else if (i < 2 * CVT_N4)   { src = Wb; dst = w2 + (size_t)INNER * DD;   o = i - CVT_N4; }
    else                       { src = Wo; dst = wo16;                      o = i - 2 * CVT_N4; }
    float4 v = reinterpret_cast<const float4*>(src)[o];
    __half2* d = reinterpret_cast<__half2*>(dst) + o * 2;
    d[0] = __floats2half2_rn(v.x, v.y);
    d[1] = __floats2half2_rn(v.z, v.w);
}

// ---------------- HMMA fp16 GEMM with ldmatrix, 3-stage pipeline ------------
#define RS 40
#define TILE_H (128 * RS)
#define TB (TILE_H * 2)
#define STAGE_B (2 * TB)
#define NSTAGE 3
#define GEMM_SMEM_BYTES (NSTAGE * STAGE_B)   // 61440

#define MMA_F16(c, a, b)                                                \
    asm volatile(                                                       \
        "mma.sync.aligned.m16n8k16.row.col.f32.f16.f16.f32 "            \
        "{%0,%1,%2,%3}, {%4,%5,%6,%7}, {%8,%9}, {%0,%1,%2,%3};"         \
        : "+f"((c)[0]), "+f"((c)[1]), "+f"((c)[2]), "+f"((c)[3])        \
        : "r"((a)[0]), "r"((a)[1]), "r"((a)[2]), "r"((a)[3]),           \
          "r"((b)[0]), "r"((b)[1]))

#define LDSM4(r0, r1, r2, r3, addr)                                     \
    asm volatile("ldmatrix.sync.aligned.m8n8.x4.shared.b16 "            \
                 "{%0,%1,%2,%3}, [%4];"                                 \
                 : "=r"(r0), "=r"(r1), "=r"(r2), "=r"(r3) : "r"(addr))

template <bool HALF_OUT>
__global__ __launch_bounds__(256, 2) void gemm_f16(
    const __half* __restrict__ A, const __half* __restrict__ B,
    void* __restrict__ Cv, const float* __restrict__ res, int N, int K)
{
    extern __shared__ uint16_t sm[];

    const int tid  = threadIdx.x;
    const int lane = tid & 31;
    const int wid  = tid >> 5;
    const int wm   = wid >> 2;
    const int wn   = wid & 3;
    const int r    = lane >> 2;
    const int cp   = (lane & 3) * 2;

    const size_t mBase = (size_t)blockIdx.y * 128;
    const size_t nBase = (size_t)blockIdx.x * 128;

    const __half* srcA = A + mBase * K;
    const __half* srcB = B + nBase * K;

    const uint32_t smem_base = smem_u32(sm);

    const uint32_t aLaneOff =
        (uint32_t)(((wm * 64 + ((lane >> 3) & 1) * 8 + (lane & 7)) * RS
                    + (lane >> 4) * 8) * 2);
    const uint32_t bLaneOff =
        (uint32_t)(((wn * 32 + ((lane >> 4) & 1) * 8 + (lane & 7)) * RS
                    + ((lane >> 3) & 1) * 8) * 2);

    const int lrow0 = tid >> 2;
    const int lseg  = tid & 3;
    auto load_stage = [&](int s, int kt) {
        uint32_t sb = smem_base + (uint32_t)s * STAGE_B;
#pragma unroll
        for (int rep = 0; rep < 2; rep++) {
            int row = lrow0 + rep * 64;
            uint32_t off = row * (RS * 2) + lseg * 16;
            size_t go = (size_t)row * K + kt * 32 + lseg * 8;
            asm volatile("cp.async.cg.shared.global [%0], [%1], 16;"
                         :: "r"(sb + off), "l"(srcA + go));
            asm volatile("cp.async.cg.shared.global [%0], [%1], 16;"
                         :: "r"(sb + TB + off), "l"(srcB + go));
        }
        asm volatile("cp.async.commit_group;" ::: "memory");
    };

    float acc[4][4][4];
#pragma unroll
    for (int i = 0; i < 4; i++)
#pragma unroll
        for (int j = 0; j < 4; j++)
#pragma unroll
            for (int q = 0; q < 4; q++) acc[i][j][q] = 0.f;

    const int nkt = K >> 5;

    load_stage(0, 0);
    load_stage(1, 1);

    int sc = 0;
    for (int kt = 0; kt < nkt; kt++) {
        if (kt + 1 < nkt) {
            asm volatile("cp.async.wait_group 1;" ::: "memory");
        } else {
            asm volatile("cp.async.wait_group 0;" ::: "memory");
        }
        __syncthreads();

        if (kt + 2 < nkt) {
            int s2 = sc + 2; if (s2 >= NSTAGE) s2 -= NSTAGE;
            load_stage(s2, kt + 2);
        }

        uint32_t sb = smem_base + (uint32_t)sc * STAGE_B;

#pragma unroll
        for (int k16 = 0; k16 < 32; k16 += 16) {
            uint32_t bh[4][2];
#pragma unroll
            for (int j = 0; j < 2; j++) {
                uint32_t ad = sb + TB + bLaneOff
                            + (uint32_t)((j * 16 * RS + k16) * 2);
                LDSM4(bh[2*j][0], bh[2*j][1], bh[2*j+1][0], bh[2*j+1][1], ad);
            }
#pragma unroll
            for (int mi = 0; mi < 4; mi++) {
                uint32_t a4[4];
                uint32_t ad = sb + aLaneOff + (uint32_t)((mi * 16 * RS + k16) * 2);
                LDSM4(a4[0], a4[1], a4[2], a4[3], ad);
#pragma unroll
                for (int ni = 0; ni < 4; ni++)
                    MMA_F16(acc[mi][ni], a4, bh[ni]);
            }
        }
        __syncthreads();
        if (++sc == NSTAGE) sc = 0;
    }

#pragma unroll
    for (int mi = 0; mi < 4; mi++) {
        size_t row0 = mBase + wm * 64 + mi * 16 + r;
#pragma unroll
        for (int ni = 0; ni < 4; ni++) {
            size_t col = nBase + wn * 32 + ni * 8 + cp;
            if (HALF_OUT) {
                __half* C = (__half*)Cv;
                *reinterpret_cast<__half2*>(C + row0 * N + col) =
                    __floats2half2_rn(acc[mi][ni][0], acc[mi][ni][1]);
                *reinterpret_cast<__half2*>(C + (row0 + 8) * N + col) =
                    __floats2half2_rn(acc[mi][ni][2], acc[mi][ni][3]);
            } else {
                float* C = (float*)Cv;
                float2 v0 = make_float2(acc[mi][ni][0], acc[mi][ni][1]);
                float2 v1 = make_float2(acc[mi][ni][2], acc[mi][ni][3]);
                if (res) {
                    float2 r0 = *reinterpret_cast<const float2*>(res + row0 * N + col);
                    float2 r1 = *reinterpret_cast<const float2*>(res + (row0 + 8) * N + col);
                    v0.x += r0.x; v0.y += r0.y;
                    v1.x += r1.x; v1.y += r1.y;
                }
                *reinterpret_cast<float2*>(C + row0 * N + col) = v0;
                *reinterpret_cast<float2*>(C + (row0 + 8) * N + col) = v1;
            }
        }
    }
}

// ---------------- scan pass 1: conv+silu -> u + chunk states ----------------
// Block = (batch, chunk). 256 threads, 4 channels each (uint2 = 8B loads).
__global__ __launch_bounds__(256) void scan_u_state_kernel(
    const uint2* __restrict__ ab,        // rows of RSU2 uint2
    uint2* __restrict__ u,               // rows of USU2 uint2
    const float* __restrict__ conv_w, const float* __restrict__ conv_b,
    const float* __restrict__ alpha, const float* __restrict__ beta,
    float* __restrict__ S)
{
    const int c = blockIdx.x & (NC - 1);
    const int b = blockIdx.x >> 6;
    const int t = threadIdx.x;
    const int i0 = t * 4;

    float w0[4], w1[4], w2[4], w3[4], w4[4], cb[4], as[4], bt[4];
#pragma unroll
    for (int l = 0; l < 4; l++) {
        w0[l] = conv_w[(i0+l)*KW+0];
        w1[l] = conv_w[(i0+l)*KW+1];
        w2[l] = conv_w[(i0+l)*KW+2];
        w3[l] = conv_w[(i0+l)*KW+3];
        w4[l] = conv_w[(i0+l)*KW+4];
        cb[l] = conv_b[i0+l];
        as[l] = 1.0f / (1.0f + __expf(-alpha[i0+l]));
        bt[l] = beta[i0+l];
    }

    const uint2* col = ab + (size_t)b * KK * RSU2 + t;
    uint2* up = u + (size_t)b * KK * USU2 + t;
    const int k0 = c * CL;

    float xm2[4] = {0,0,0,0}, xm1[4] = {0,0,0,0}, x0[4], x1[4], s[4] = {0,0,0,0};
    if (c > 0) {
        h4_to_f4(col[(size_t)(k0-2) * RSU2], xm2);
        h4_to_f4(col[(size_t)(k0-1) * RSU2], xm1);
    }
    h4_to_f4(col[(size_t)k0 * RSU2], x0);
    h4_to_f4(col[(size_t)(k0+1) * RSU2], x1);

#pragma unroll
    for (int k = 0; k < CL; k += 8) {
        uint2 xr[8];
#pragma unroll
        for (int j = 0; j < 8; j++) {
            int kk = k0 + k + 2 + j;
            xr[j] = (kk < KK) ? col[(size_t)kk * RSU2] : make_uint2(0u, 0u);
        }
#pragma unroll
        for (int j = 0; j < 8; j++) {
            float x2[4], uf[4];
            h4_to_f4(xr[j], x2);
#pragma unroll
            for (int l = 0; l < 4; l++) {
                float cc = fmaf(w0[l], xm2[l], fmaf(w1[l], xm1[l],
                           fmaf(w2[l], x0[l], fmaf(w3[l], x1[l],
                           fmaf(w4[l], x2[l], cb[l])))));
                float uu = __fdividef(cc, 1.0f + __expf(-cc));
                s[l] = fmaf(as[l], s[l], bt[l] * uu);
                uf[l] = uu;
                xm2[l] = xm1[l]; xm1[l] = x0[l]; x0[l] = x1[l]; x1[l] = x2[l];
            }
            up[(size_t)(k0 + k + j) * USU2] = f4_to_h4(uf);
        }
    }

    *reinterpret_cast<float4*>(&S[((size_t)b * NC + c) * INNER + i0]) =
        make_float4(s[0], s[1], s[2], s[3]);
}

// ---------------- scan pass 2: prefix of chunk states ----------------
__global__ __launch_bounds__(256) void scan_prefix_kernel(
    const float* __restrict__ S, const float* __restrict__ alpha,
    float* __restrict__ Sin)
{
    int idx = blockIdx.x * 256 + threadIdx.x;   // 0 .. BB*INNER-1
    int i = idx & (INNER - 1);
    int b = idx >> 10;

    float a = 1.0f / (1.0f + __expf(-alpha[i]));
    float aL = a;
#pragma unroll
    for (int q = 0; q < 5; q++) aL *= aL;       // a^32

    float s = 0.f;
#pragma unroll
    for (int c = 0; c < NC; c++) {
        size_t o = ((size_t)b * NC + c) * INNER + i;
        Sin[o] = s;
        s = fmaf(aL, s, S[o]);
    }
}

// ---------------- scan pass 3: apply + gate -> g (fp16) ----------------
__global__ __launch_bounds__(256) void scan_apply_kernel(
    const uint2* __restrict__ ab,
    const uint2* __restrict__ u,
    const float* __restrict__ Sin,
    uint2* __restrict__ g,
    const float* __restrict__ alpha, const float* __restrict__ beta,
    const float* __restrict__ gamma, const float* __restrict__ delta)
{
    const int c = blockIdx.x & (NC - 1);
    const int b = blockIdx.x >> 6;
    const int t = threadIdx.x;
    const int i0 = t * 4;

    float as[4], bt[4], gm[4], dl[4];
#pragma unroll
    for (int l = 0; l < 4; l++) {
        as[l] = 1.0f / (1.0f + __expf(-alpha[i0+l]));
        bt[l] = beta[i0+l];
        gm[l] = gamma[i0+l];
        dl[l] = delta[i0+l];
    }

    float s[4];
    {
        float4 sv = *reinterpret_cast<const float4*>(
            &Sin[((size_t)b * NC + c) * INNER + i0]);
        s[0] = sv.x; s[1] = sv.y; s[2] = sv.z; s[3] = sv.w;
    }

    const uint2* bp = ab + (size_t)b * KK * RSU2 + (RSU2 / 2) + t;
    const uint2* up = u + (size_t)b * KK * USU2 + t;
    uint2* gp = g + (size_t)b * KK * USU2 + t;
    const int k0 = c * CL;

#pragma unroll
    for (int k = 0; k < CL; k += 8) {
        uint2 ur[8], br[8];
#pragma unroll
        for (int j = 0; j < 8; j++)
            ur[j] = up[(size_t)(k0 + k + j) * USU2];
#pragma unroll
        for (int j = 0; j < 8; j++)
            br[j] = bp[(size_t)(k0 + k + j) * RSU2];
#pragma unroll
        for (int j = 0; j < 8; j++) {
            float uf[4], bf[4], gf[4];
            h4_to_f4(ur[j], uf);
            h4_to_f4(br[j], bf);
#pragma unroll
            for (int l = 0; l < 4; l++) {
                s[l] = fmaf(as[l], s[l], bt[l] * uf[l]);
                float y = fmaf(gm[l], s[l], dl[l] * uf[l]);
                gf[l] = y * bf[l];
            }
            gp[(size_t)(k0 + k + j) * USU2] = f4_to_h4(gf);
        }
    }
}

// ---------------- launch ----------------
extern "C" void kernel_launch(void* const* d_in, const int* in_sizes, int n_in,
                              void* d_out, int out_size)
{
    const float* x      = (const float*)d_in[0];
    const float* norm_w = (const float*)d_in[1];
    const float* Wa     = (const float*)d_in[2];
    const float* Wb     = (const float*)d_in[3];
    const float* conv_w = (const float*)d_in[4];
    const float* conv_b = (const float*)d_in[5];
    const float* alpha  = (const float*)d_in[6];
    const float* beta   = (const float*)d_in[7];
    const float* gamma  = (const float*)d_in[8];
    const float* delta  = (const float*)d_in[9];
    const float* Wout   = (const float*)d_in[10];
    float* out = (float*)d_out;

    float *st, *sin;
    __half *ab, *u, *h16, *g16, *w2, *wo16;
    cudaGetSymbolAddress((void**)&ab,   g_ab);
    cudaGetSymbolAddress((void**)&u,    g_u);
    cudaGetSymbolAddress((void**)&st,   g_state);
    cudaGetSymbolAddress((void**)&sin,  g_sin);
    cudaGetSymbolAddress((void**)&h16,  g_h16);
    cudaGetSymbolAddress((void**)&g16,  g_g16);
    cudaGetSymbolAddress((void**)&w2,   g_w2);
    cudaGetSymbolAddress((void**)&wo16, g_wo16);

    cudaFuncSetAttribute(gemm_f16<true>,
                         cudaFuncAttributeMaxDynamicSharedMemorySize, GEMM_SMEM_BYTES);
    cudaFuncSetAttribute(gemm_f16<false>,
                         cudaFuncAttributeMaxDynamicSharedMemorySize, GEMM_SMEM_BYTES);

    // 1) rmsnorm -> fp16
    rmsnorm_kernel<<<MM / 8, 256>>>(x, norm_w, h16);

    // 2) all weight conversions in one launch
    cvt_all_kernel<<<(3 * CVT_N4) / 256, 256>>>(Wa, Wb, Wout, w2, wo16);

    // 3) [a|b] = h @ [Wa;Wb]^T   (M=32768, N=2048, K=512), fp16 out
    {
        dim3 grid(W2 / 128, MM / 128);
        gemm_f16<true><<<grid, 256, GEMM_SMEM_BYTES>>>(h16, w2, ab, nullptr, W2, DD);
    }

    // 4) chunked scan: u+state, prefix, apply
    scan_u_state_kernel<<<BB * NC, 256>>>(
        (const uint2*)ab, (uint2*)u, conv_w, conv_b, alpha, beta, st);
    scan_prefix_kernel<<<BB * INNER / 256, 256>>>(st, alpha, sin);
    scan_apply_kernel<<<BB * NC, 256>>>(
        (const uint2*)ab, (const uint2*)u, sin, (uint2*)g16,
        alpha, beta, gamma, delta);

    // 5) out = x + g @ Wout^T   (M=32768, N=512, K=1024), fp32 out + residual
    {
        dim3 grid(DD / 128, MM / 128);
        gemm_f16<false><<<grid, 256, GEMM_SMEM_BYTES>>>(g16, wo16, out, x, DD, INNER);
    }
}

// round 12
// speedup vs baseline: 1.0642x; 1.0471x over previous
#include <cuda_runtime.h>
#include <cuda_fp16.h>
#include <cstdint>

// ---------------- problem constants ----------------
#define BB    16
#define KK    2048
#define DD    512
#define INNER 1024
#define W2    (2*INNER)    // combined a|b row stride (halves)
#define KW    5
#define MM    (BB*KK)      // 32768
#define EPSV  1e-5f
#define NC    128          // scan chunks
#define CL    (KK/NC)      // 16
#define RSU2  (W2/4)       // uint2 per ab row (512)
#define USU2  (INNER/4)    // uint2 per u/g row (256)

// ---------------- scratch (device globals) ----------------
__device__ __half  g_ab [(size_t)MM * W2];     // [M, 2048]: a | b (fp16) 128MB
__device__ __half  g_u  [(size_t)MM * INNER];  // conv+silu out (fp16)  64MB
__device__ __half  g_h16[(size_t)MM * DD];     // rmsnorm out (fp16)
__device__ __half  g_g16[(size_t)MM * INNER];  // scan out    (fp16)
__device__ __half  g_w2 [W2 * DD];             // [Wa;Wb] fp16
__device__ __half  g_wo16[DD * INNER];
__device__ float   g_state[BB * NC * INNER];   // chunk-local final states
__device__ float   g_sin  [BB * NC * INNER];   // carried-in states

__device__ __forceinline__ uint32_t smem_u32(const void* p) {
    uint32_t a;
    asm("{ .reg .u64 t; cvta.to.shared.u64 t, %1; cvt.u32.u64 %0, t; }"
        : "=r"(a) : "l"(p));
    return a;
}

// fast single-MUFU silu: 0.5c + 0.5c*tanh(0.5c)
__device__ __forceinline__ float silu_fast(float c) {
    float h = 0.5f * c;
    float t;
    asm("tanh.approx.f32 %0, %1;" : "=f"(t) : "f"(h));
    return fmaf(h, t, h);
}

// 4-half <-> 4-float helpers
__device__ __forceinline__ void h4_to_f4(uint2 v, float* f) {
    __half2 lo = *reinterpret_cast<__half2*>(&v.x);
    __half2 hi = *reinterpret_cast<__half2*>(&v.y);
    float2 a = __half22float2(lo), b = __half22float2(hi);
    f[0] = a.x; f[1] = a.y; f[2] = b.x; f[3] = b.y;
}
__device__ __forceinline__ uint2 f4_to_h4(const float* f) {
    __half2 lo = __floats2half2_rn(f[0], f[1]);
    __half2 hi = __floats2half2_rn(f[2], f[3]);
    uint2 r;
    r.x = *reinterpret_cast<uint32_t*>(&lo);
    r.y = *reinterpret_cast<uint32_t*>(&hi);
    return r;
}

// ---------------- rmsnorm -> fp16 ----------------
__global__ __launch_bounds__(256) void rmsnorm_kernel(
    const float* __restrict__ x, const float* __restrict__ w,
    __half* __restrict__ h16)
{
    int row  = blockIdx.x * 8 + (threadIdx.x >> 5);
    int lane = threadIdx.x & 31;
    const float4* xp = reinterpret_cast<const float4*>(x + (size_t)row * DD);
    const float4* wp = reinterpret_cast<const float4*>(w);

    float4 v[4];
    float ss = 0.f;
#pragma unroll
    for (int j = 0; j < 4; j++) {
        v[j] = xp[lane + 32 * j];
        ss += v[j].x * v[j].x + v[j].y * v[j].y + v[j].z * v[j].z + v[j].w * v[j].w;
    }
#pragma unroll
    for (int off = 16; off > 0; off >>= 1)
        ss += __shfl_xor_sync(0xffffffffu, ss, off);

    float r = rsqrtf(ss * (1.0f / DD) + EPSV);

    __half* hb = h16 + (size_t)row * DD;
#pragma unroll
    for (int j = 0; j < 4; j++) {
        float4 wv = wp[lane + 32 * j];
        int col = (lane + 32 * j) * 4;
        __half2* hp = reinterpret_cast<__half2*>(hb + col);
        hp[0] = __floats2half2_rn(v[j].x * r * wv.x, v[j].y * r * wv.y);
        hp[1] = __floats2half2_rn(v[j].z * r * wv.z, v[j].w * r * wv.w);
    }
}

// ---------------- combined fp32 -> fp16 cast (all three weights) ------------
#define CVT_N4 (INNER * DD / 4)
__global__ __launch_bounds__(256) void cvt_all_kernel(
    const float* __restrict__ Wa, const float* __restrict__ Wb,
    const float* __restrict__ Wo,
    __half* __restrict__ w2, __half* __restrict__ wo16)
{
    int i = blockIdx.x * 256 + threadIdx.x;
    const float* src;
    __half* dst;
    int o;
    if (i < CVT_N4)            { src = Wa; dst = w2;                        o = i; }
    else if (i < 2 * CVT_N4)   { src = Wb; dst = w2 + (size_t)INNER * DD;   o = i - CVT_N4; }
    else                       { src = Wo; dst = wo16;                      o = i - 2 * CVT_N4; }
    float4 v = reinterpret_cast<const float4*>(src)[o];
    __half2* d = reinterpret_cast<__half2*>(dst) + o * 2;
    d[0] = __floats2half2_rn(v.x, v.y);
    d[1] = __floats2half2_rn(v.z, v.w);
}

// ---------------- HMMA fp16 GEMM with ldmatrix, 3-stage pipeline ------------
#define RS 40
#define TILE_H (128 * RS)
#define TB (TILE_H * 2)
#define STAGE_B (2 * TB)
#define NSTAGE 3
#define GEMM_SMEM_BYTES (NSTAGE * STAGE_B)   // 61440

#define MMA_F16(c, a, b)                                                \
    asm volatile(                                                       \
        "mma.sync.aligned.m16n8k16.row.col.f32.f16.f16.f32 "            \
        "{%0,%1,%2,%3}, {%4,%5,%6,%7}, {%8,%9}, {%0,%1,%2,%3};"         \
        : "+f"((c)[0]), "+f"((c)[1]), "+f"((c)[2]), "+f"((c)[3])        \
        : "r"((a)[0]), "r"((a)[1]), "r"((a)[2]), "r"((a)[3]),           \
          "r"((b)[0]), "r"((b)[1]))

#define LDSM4(r0, r1, r2, r3, addr)                                     \
    asm volatile("ldmatrix.sync.aligned.m8n8.x4.shared.b16 "            \
                 "{%0,%1,%2,%3}, [%4];"                                 \
                 : "=r"(r0), "=r"(r1), "=r"(r2), "=r"(r3) : "r"(addr))

template <bool HALF_OUT>
__global__ __launch_bounds__(256, 2) void gemm_f16(
    const __half* __restrict__ A, const __half* __restrict__ B,
    void* __restrict__ Cv, const float* __restrict__ res, int N, int K)
{
    extern __shared__ uint16_t sm[];

    const int tid  = threadIdx.x;
    const int lane = tid & 31;
    const int wid  = tid >> 5;
    const int wm   = wid >> 2;
    const int wn   = wid & 3;
    const int r    = lane >> 2;
    const int cp   = (lane & 3) * 2;

    const size_t mBase = (size_t)blockIdx.y * 128;
    const size_t nBase = (size_t)blockIdx.x * 128;

    const __half* srcA = A + mBase * K;
    const __half* srcB = B + nBase * K;

    const uint32_t smem_base = smem_u32(sm);

    const uint32_t aLaneOff =
        (uint32_t)(((wm * 64 + ((lane >> 3) & 1) * 8 + (lane & 7)) * RS
                    + (lane >> 4) * 8) * 2);
    const uint32_t bLaneOff =
        (uint32_t)(((wn * 32 + ((lane >> 4) & 1) * 8 + (lane & 7)) * RS
                    + ((lane >> 3) & 1) * 8) * 2);

    const int lrow0 = tid >> 2;
    const int lseg  = tid & 3;
    auto load_stage = [&](int s, int kt) {
        uint32_t sb = smem_base + (uint32_t)s * STAGE_B;
#pragma unroll
        for (int rep = 0; rep < 2; rep++) {
            int row = lrow0 + rep * 64;
            uint32_t off = row * (RS * 2) + lseg * 16;
            size_t go = (size_t)row * K + kt * 32 + lseg * 8;
            asm volatile("cp.async.cg.shared.global [%0], [%1], 16;"
                         :: "r"(sb + off), "l"(srcA + go));
            asm volatile("cp.async.cg.shared.global [%0], [%1], 16;"
                         :: "r"(sb + TB + off), "l"(srcB + go));
        }
        asm volatile("cp.async.commit_group;" ::: "memory");
    };

    float acc[4][4][4];
#pragma unroll
    for (int i = 0; i < 4; i++)
#pragma unroll
        for (int j = 0; j < 4; j++)
#pragma unroll
            for (int q = 0; q < 4; q++) acc[i][j][q] = 0.f;

    const int nkt = K >> 5;

    load_stage(0, 0);
    load_stage(1, 1);

    int sc = 0;
    for (int kt = 0; kt < nkt; kt++) {
        if (kt + 1 < nkt) {
            asm volatile("cp.async.wait_group 1;" ::: "memory");
        } else {
            asm volatile("cp.async.wait_group 0;" ::: "memory");
        }
        __syncthreads();

        if (kt + 2 < nkt) {
            int s2 = sc + 2; if (s2 >= NSTAGE) s2 -= NSTAGE;
            load_stage(s2, kt + 2);
        }

        uint32_t sb = smem_base + (uint32_t)sc * STAGE_B;

#pragma unroll
        for (int k16 = 0; k16 < 32; k16 += 16) {
            uint32_t bh[4][2];
#pragma unroll
            for (int j = 0; j < 2; j++) {
                uint32_t ad = sb + TB + bLaneOff
                            + (uint32_t)((j * 16 * RS + k16) * 2);
                LDSM4(bh[2*j][0], bh[2*j][1], bh[2*j+1][0], bh[2*j+1][1], ad);
            }
#pragma unroll
            for (int mi = 0; mi < 4; mi++) {
                uint32_t a4[4];
                uint32_t ad = sb + aLaneOff + (uint32_t)((mi * 16 * RS + k16) * 2);
                LDSM4(a4[0], a4[1], a4[2], a4[3], ad);
#pragma unroll
                for (int ni = 0; ni < 4; ni++)
                    MMA_F16(acc[mi][ni], a4, bh[ni]);
            }
        }
        __syncthreads();
        if (++sc == NSTAGE) sc = 0;
    }

#pragma unroll
    for (int mi = 0; mi < 4; mi++) {
        size_t row0 = mBase + wm * 64 + mi * 16 + r;
#pragma unroll
        for (int ni = 0; ni < 4; ni++) {
            size_t col = nBase + wn * 32 + ni * 8 + cp;
            if (HALF_OUT) {
                __half* C = (__half*)Cv;
                *reinterpret_cast<__half2*>(C + row0 * N + col) =
                    __floats2half2_rn(acc[mi][ni][0], acc[mi][ni][1]);
                *reinterpret_cast<__half2*>(C + (row0 + 8) * N + col) =
                    __floats2half2_rn(acc[mi][ni][2], acc[mi][ni][3]);
            } else {
                float* C = (float*)Cv;
                float2 v0 = make_float2(acc[mi][ni][0], acc[mi][ni][1]);
                float2 v1 = make_float2(acc[mi][ni][2], acc[mi][ni][3]);
                if (res) {
                    float2 r0 = *reinterpret_cast<const float2*>(res + row0 * N + col);
                    float2 r1 = *reinterpret_cast<const float2*>(res + (row0 + 8) * N + col);
                    v0.x += r0.x; v0.y += r0.y;
                    v1.x += r1.x; v1.y += r1.y;
                }
                *reinterpret_cast<float2*>(C + row0 * N + col) = v0;
                *reinterpret_cast<float2*>(C + (row0 + 8) * N + col) = v1;
            }
        }
    }
}

// ---------------- scan pass 1: conv+silu -> u + chunk states ----------------
// Block = (batch, chunk). 256 threads, 4 channels each.
__global__ __launch_bounds__(256, 3) void scan_u_state_kernel(
    const uint2* __restrict__ ab,
    uint2* __restrict__ u,
    const float* __restrict__ conv_w, const float* __restrict__ conv_b,
    const float* __restrict__ alpha, const float* __restrict__ beta,
    float* __restrict__ S)
{
    const int c = blockIdx.x & (NC - 1);
    const int b = blockIdx.x >> 7;
    const int t = threadIdx.x;
    const int i0 = t * 4;

    float w0[4], w1[4], w2[4], w3[4], w4[4], cb[4], as[4], bt[4];
#pragma unroll
    for (int l = 0; l < 4; l++) {
        w0[l] = conv_w[(i0+l)*KW+0];
        w1[l] = conv_w[(i0+l)*KW+1];
        w2[l] = conv_w[(i0+l)*KW+2];
        w3[l] = conv_w[(i0+l)*KW+3];
        w4[l] = conv_w[(i0+l)*KW+4];
        cb[l] = conv_b[i0+l];
        as[l] = 1.0f / (1.0f + __expf(-alpha[i0+l]));
        bt[l] = beta[i0+l];
    }

    const uint2* col = ab + (size_t)b * KK * RSU2 + t;
    uint2* up = u + (size_t)b * KK * USU2 + t;
    const int k0 = c * CL;

    float xm2[4] = {0,0,0,0}, xm1[4] = {0,0,0,0}, x0[4], x1[4], s[4] = {0,0,0,0};
    if (c > 0) {
        h4_to_f4(col[(size_t)(k0-2) * RSU2], xm2);
        h4_to_f4(col[(size_t)(k0-1) * RSU2], xm1);
    }
    h4_to_f4(col[(size_t)k0 * RSU2], x0);
    h4_to_f4(col[(size_t)(k0+1) * RSU2], x1);

#pragma unroll
    for (int k = 0; k < CL; k += 4) {
        uint2 xr[4];
#pragma unroll
        for (int j = 0; j < 4; j++) {
            int kk = k0 + k + 2 + j;
            xr[j] = (kk < KK) ? col[(size_t)kk * RSU2] : make_uint2(0u, 0u);
        }
#pragma unroll
        for (int j = 0; j < 4; j++) {
            float x2[4], uf[4];
            h4_to_f4(xr[j], x2);
#pragma unroll
            for (int l = 0; l < 4; l++) {
                float cc = fmaf(w0[l], xm2[l], fmaf(w1[l], xm1[l],
                           fmaf(w2[l], x0[l], fmaf(w3[l], x1[l],
                           fmaf(w4[l], x2[l], cb[l])))));
                float uu = silu_fast(cc);
                s[l] = fmaf(as[l], s[l], bt[l] * uu);
                uf[l] = uu;
                xm2[l] = xm1[l]; xm1[l] = x0[l]; x0[l] = x1[l]; x1[l] = x2[l];
            }
            up[(size_t)(k0 + k + j) * USU2] = f4_to_h4(uf);
        }
    }

    *reinterpret_cast<float4*>(&S[((size_t)b * NC + c) * INNER + i0]) =
        make_float4(s[0], s[1], s[2], s[3]);
}

// ---------------- scan pass 2: prefix of chunk states ----------------
__global__ __launch_bounds__(256) void scan_prefix_kernel(
    const float* __restrict__ S, const float* __restrict__ alpha,
    float* __restrict__ Sin)
{
    int idx = blockIdx.x * 256 + threadIdx.x;   // 0 .. BB*INNER-1
    int i = idx & (INNER - 1);
    int b = idx >> 10;

    float a = 1.0f / (1.0f + __expf(-alpha[i]));
    float aL = a;
#pragma unroll
    for (int q = 0; q < 4; q++) aL *= aL;       // a^16

    float s = 0.f;
#pragma unroll
    for (int c = 0; c < NC; c++) {
        size_t o = ((size_t)b * NC + c) * INNER + i;
        Sin[o] = s;
        s = fmaf(aL, s, S[o]);
    }
}

// ---------------- scan pass 3: apply + gate -> g (fp16) ----------------
__global__ __launch_bounds__(256, 4) void scan_apply_kernel(
    const uint2* __restrict__ ab,
    const uint2* __restrict__ u,
    const float* __restrict__ Sin,
    uint2* __restrict__ g,
    const float* __restrict__ alpha, const float* __restrict__ beta,
    const float* __restrict__ gamma, const float* __restrict__ delta)
{
    const int c = blockIdx.x & (NC - 1);
    const int b = blockIdx.x >> 7;
    const int t = threadIdx.x;
    const int i0 = t * 4;

    float as[4], bt[4], gm[4], dl[4];
#pragma unroll
    for (int l = 0; l < 4; l++) {
        as[l] = 1.0f / (1.0f + __expf(-alpha[i0+l]));
        bt[l] = beta[i0+l];
        gm[l] = gamma[i0+l];
        dl[l] = delta[i0+l];
    }

    float s[4];
    {
        float4 sv = *reinterpret_cast<const float4*>(
            &Sin[((size_t)b * NC + c) * INNER + i0]);
        s[0] = sv.x; s[1] = sv.y; s[2] = sv.z; s[3] = sv.w;
    }

    const uint2* bp = ab + (size_t)b * KK * RSU2 + (RSU2 / 2) + t;
    const uint2* up = u + (size_t)b * KK * USU2 + t;
    uint2* gp = g + (size_t)b * KK * USU2 + t;
    const int k0 = c * CL;

#pragma unroll
    for (int k = 0; k < CL; k += 4) {
        uint2 ur[4], br[4];
#pragma unroll
        for (int j = 0; j < 4; j++)
            ur[j] = up[(size_t)(k0 + k + j) * USU2];
#pragma unroll
        for (int j = 0; j < 4; j++)
            br[j] = bp[(size_t)(k0 + k + j) * RSU2];
#pragma unroll
        for (int j = 0; j < 4; j++) {
            float uf[4], bf[4], gf[4];
            h4_to_f4(ur[j], uf);
            h4_to_f4(br[j], bf);
#pragma unroll
            for (int l = 0; l < 4; l++) {
                s[l] = fmaf(as[l], s[l], bt[l] * uf[l]);
                float y = fmaf(gm[l], s[l], dl[l] * uf[l]);
                gf[l] = y * bf[l];
            }
            gp[(size_t)(k0 + k + j) * USU2] = f4_to_h4(gf);
        }
    }
}

// ---------------- launch ----------------
extern "C" void kernel_launch(void* const* d_in, const int* in_sizes, int n_in,
                              void* d_out, int out_size)
{
    const float* x      = (const float*)d_in[0];
    const float* norm_w = (const float*)d_in[1];
    const float* Wa     = (const float*)d_in[2];
    const float* Wb     = (const float*)d_in[3];
    const float* conv_w = (const float*)d_in[4];
    const float* conv_b = (const float*)d_in[5];
    const float* alpha  = (const float*)d_in[6];
    const float* beta   = (const float*)d_in[7];
    const float* gamma  = (const float*)d_in[8];
    const float* delta  = (const float*)d_in[9];
    const float* Wout   = (const float*)d_in[10];
    float* out = (float*)d_out;

    float *st, *sin;
    __half *ab, *u, *h16, *g16, *w2, *wo16;
    cudaGetSymbolAddress((void**)&ab,   g_ab);
    cudaGetSymbolAddress((void**)&u,    g_u);
    cudaGetSymbolAddress((void**)&st,   g_state);
    cudaGetSymbolAddress((void**)&sin,  g_sin);
    cudaGetSymbolAddress((void**)&h16,  g_h16);
    cudaGetSymbolAddress((void**)&g16,  g_g16);
    cudaGetSymbolAddress((void**)&w2,   g_w2);
    cudaGetSymbolAddress((void**)&wo16, g_wo16);

    cudaFuncSetAttribute(gemm_f16<true>,
                         cudaFuncAttributeMaxDynamicSharedMemorySize, GEMM_SMEM_BYTES);
    cudaFuncSetAttribute(gemm_f16<false>,
                         cudaFuncAttributeMaxDynamicSharedMemorySize, GEMM_SMEM_BYTES);

    // 1) rmsnorm -> fp16
    rmsnorm_kernel<<<MM / 8, 256>>>(x, norm_w, h16);

    // 2) all weight conversions in one launch
    cvt_all_kernel<<<(3 * CVT_N4) / 256, 256>>>(Wa, Wb, Wout, w2, wo16);

    // 3) [a|b] = h @ [Wa;Wb]^T   (M=32768, N=2048, K=512), fp16 out
    {
        dim3 grid(W2 / 128, MM / 128);
        gemm_f16<true><<<grid, 256, GEMM_SMEM_BYTES>>>(h16, w2, ab, nullptr, W2, DD);
    }

    // 4) chunked scan: u+state, prefix, apply
    scan_u_state_kernel<<<BB * NC, 256>>>(
        (const uint2*)ab, (uint2*)u, conv_w, conv_b, alpha, beta, st);
    scan_prefix_kernel<<<BB * INNER / 256, 256>>>(st, alpha, sin);
    scan_apply_kernel<<<BB * NC, 256>>>(
        (const uint2*)ab, (const uint2*)u, sin, (uint2*)g16,
        alpha, beta, gamma, delta);

    // 5) out = x + g @ Wout^T   (M=32768, N=512, K=1024), fp32 out + residual
    {
        dim3 grid(DD / 128, MM / 128);
        gemm_f16<false><<<grid, 256, GEMM_SMEM_BYTES>>>(g16, wo16, out, x, DD, INNER);
    }
}